// round 4
// baseline (speedup 1.0000x reference)
#include <cuda_runtime.h>
#include <cuda_bf16.h>
#include <math.h>
#include <stdint.h>

// Problem dims (fixed by the dataset)
#define BATCH 1024
#define SEQ   512
#define DIM   768

// Scratch (allocation-free rule: __device__ globals)
__device__ float g_pooled[BATCH * DIM];
__device__ float g_hidden[BATCH * DIM];

// ---------------------------------------------------------------------------
// Kernel 1: masked sum pooling (R1 design, at DRAM roofline; + streaming loads)
// ---------------------------------------------------------------------------
__device__ __forceinline__ float2 ldcs_f2(const float2* p)
{
    float2 v;
    asm volatile("ld.global.cs.v2.f32 {%0,%1}, [%2];"
                 : "=f"(v.x), "=f"(v.y) : "l"(p));
    return v;
}

__global__ __launch_bounds__(384) void pool_kernel(
    const float* __restrict__ x,      // [BATCH, SEQ, DIM]
    const int*   __restrict__ mask)   // [BATCH, SEQ]
{
    __shared__ int s_idx[SEQ];
    __shared__ int s_cnt;

    const int b   = blockIdx.x;
    const int tid = threadIdx.x;

    if (tid == 0) s_cnt = 0;
    __syncthreads();

    const int* mrow = mask + (size_t)b * SEQ;
    for (int s = tid; s < SEQ; s += 384) {
        if (mrow[s] != 0) {
            int p = atomicAdd(&s_cnt, 1);
            s_idx[p] = s;
        }
    }
    __syncthreads();

    const int cnt = s_cnt;
    const float2* base = reinterpret_cast<const float2*>(x + (size_t)b * SEQ * DIM);
    const int rs2 = DIM / 2;

    float2 acc; acc.x = 0.f; acc.y = 0.f;

    int i = 0;
    for (; i + 4 <= cnt; i += 4) {
        int s0 = s_idx[i + 0];
        int s1 = s_idx[i + 1];
        int s2 = s_idx[i + 2];
        int s3 = s_idx[i + 3];
        float2 v0 = ldcs_f2(base + (size_t)s0 * rs2 + tid);
        float2 v1 = ldcs_f2(base + (size_t)s1 * rs2 + tid);
        float2 v2 = ldcs_f2(base + (size_t)s2 * rs2 + tid);
        float2 v3 = ldcs_f2(base + (size_t)s3 * rs2 + tid);
        acc.x += (v0.x + v1.x) + (v2.x + v3.x);
        acc.y += (v0.y + v1.y) + (v2.y + v3.y);
    }
    for (; i < cnt; i++) {
        float2 v = ldcs_f2(base + (size_t)s_idx[i] * rs2 + tid);
        acc.x += v.x;
        acc.y += v.y;
    }

    reinterpret_cast<float2*>(g_pooled + (size_t)b * DIM)[tid] = acc;
}

// ---------------------------------------------------------------------------
// Kernel 2: C = tanh(A @ B + bias), error-compensated TF32 tensor-core GEMM.
// R2 geometry (BM=BN=64, BK=32, 128 thr, 2x2 warps, 192 blocks, multi-CTA/SM
// occupancy for latency hiding) + split-ONCE-at-store: smem holds (hi,lo)
// float2, inner loop is pure LDS.64 + MMA (no per-fragment ALU).
// ---------------------------------------------------------------------------
#define BM 64
#define BN 64
#define BK 32
#define ASL2 65   // As2 row stride in float2 (64 m + 1 pad)
#define BSL2 65   // Bs2 row stride in float2 (64 n + 1 pad)

__device__ __forceinline__ float2 split_tf32_f2(float x)
{
    uint32_t hb = __float_as_uint(x) & 0xFFFFE000u;
    float hi = __uint_as_float(hb);
    float2 r; r.x = hi; r.y = x - hi;
    return r;
}

__device__ __forceinline__ void mma_tf32(
    float c[4], uint32_t a0, uint32_t a1, uint32_t a2, uint32_t a3,
    uint32_t b0, uint32_t b1)
{
    asm volatile(
        "mma.sync.aligned.m16n8k8.row.col.f32.tf32.tf32.f32 "
        "{%0,%1,%2,%3}, {%4,%5,%6,%7}, {%8,%9}, {%0,%1,%2,%3};\n"
        : "+f"(c[0]), "+f"(c[1]), "+f"(c[2]), "+f"(c[3])
        : "r"(a0), "r"(a1), "r"(a2), "r"(a3), "r"(b0), "r"(b1));
}

__global__ __launch_bounds__(128) void gemm_tf32_bias_tanh(
    const float* __restrict__ A,
    const float* __restrict__ Bm,
    const float* __restrict__ bias,
    float* __restrict__ C,
    int M, int N, int K)
{
    __shared__ float2 As2[BK][ASL2];   // As2[k][m] = (hi,lo)
    __shared__ float2 Bs2[BK][BSL2];   // Bs2[k][n] = (hi,lo)

    const int tid  = threadIdx.x;
    const int lane = tid & 31;
    const int warp = tid >> 5;       // 0..3
    const int gid  = lane >> 2;      // 0..7
    const int tig  = lane & 3;       // 0..3
    const int warpM = (warp & 1) * 32;
    const int warpN = (warp >> 1) * 32;

    const int m0 = blockIdx.y * BM;
    const int n0 = blockIdx.x * BN;

    float acc[2][4][4];
#pragma unroll
    for (int mt = 0; mt < 2; mt++)
#pragma unroll
        for (int nt = 0; nt < 4; nt++)
#pragma unroll
            for (int r = 0; r < 4; r++)
                acc[mt][nt][r] = 0.f;

    for (int k0 = 0; k0 < K; k0 += BK) {
        // --- A tile: 64x32 floats = 512 float4, 4/thread; split+transpose ---
#pragma unroll
        for (int l = 0; l < 4; l++) {
            int id = tid + l * 128;          // 0..511
            int ar = id >> 3;                // 0..63 (m)
            int ac = (id & 7) << 2;          // 0..28 (k)
            float4 v = *reinterpret_cast<const float4*>(
                A + (size_t)(m0 + ar) * K + k0 + ac);
            As2[ac + 0][ar] = split_tf32_f2(v.x);
            As2[ac + 1][ar] = split_tf32_f2(v.y);
            As2[ac + 2][ar] = split_tf32_f2(v.z);
            As2[ac + 3][ar] = split_tf32_f2(v.w);
        }
        // --- B tile: 32x64 floats = 512 float4, 4/thread; split ---
#pragma unroll
        for (int l = 0; l < 4; l++) {
            int id = tid + l * 128;
            int br = id >> 4;                // 0..31 (k)
            int bc = (id & 15) << 2;         // 0..60 (n)
            float4 v = *reinterpret_cast<const float4*>(
                Bm + (size_t)(k0 + br) * N + n0 + bc);
            Bs2[br][bc + 0] = split_tf32_f2(v.x);
            Bs2[br][bc + 1] = split_tf32_f2(v.y);
            Bs2[br][bc + 2] = split_tf32_f2(v.z);
            Bs2[br][bc + 3] = split_tf32_f2(v.w);
        }
        __syncthreads();

#pragma unroll
        for (int ks = 0; ks < 4; ks++) {
            const int kb = ks * 8;

            float2 af[2][4];
#pragma unroll
            for (int mt = 0; mt < 2; mt++) {
                const int rm = warpM + mt * 16 + gid;
                af[mt][0] = As2[kb + tig    ][rm    ];
                af[mt][1] = As2[kb + tig    ][rm + 8];
                af[mt][2] = As2[kb + tig + 4][rm    ];
                af[mt][3] = As2[kb + tig + 4][rm + 8];
            }
            float2 bf[4][2];
#pragma unroll
            for (int nt = 0; nt < 4; nt++) {
                const int nn = warpN + nt * 8 + gid;
                bf[nt][0] = Bs2[kb + tig    ][nn];
                bf[nt][1] = Bs2[kb + tig + 4][nn];
            }

#pragma unroll
            for (int mt = 0; mt < 2; mt++) {
                const uint32_t ah0 = __float_as_uint(af[mt][0].x);
                const uint32_t ah1 = __float_as_uint(af[mt][1].x);
                const uint32_t ah2 = __float_as_uint(af[mt][2].x);
                const uint32_t ah3 = __float_as_uint(af[mt][3].x);
                const uint32_t al0 = __float_as_uint(af[mt][0].y);
                const uint32_t al1 = __float_as_uint(af[mt][1].y);
                const uint32_t al2 = __float_as_uint(af[mt][2].y);
                const uint32_t al3 = __float_as_uint(af[mt][3].y);
#pragma unroll
                for (int nt = 0; nt < 4; nt++) {
                    const uint32_t bh0 = __float_as_uint(bf[nt][0].x);
                    const uint32_t bh1 = __float_as_uint(bf[nt][1].x);
                    const uint32_t bl0 = __float_as_uint(bf[nt][0].y);
                    const uint32_t bl1 = __float_as_uint(bf[nt][1].y);
                    mma_tf32(acc[mt][nt], ah0, ah1, ah2, ah3, bh0, bh1);
                    mma_tf32(acc[mt][nt], ah0, ah1, ah2, ah3, bl0, bl1);
                    mma_tf32(acc[mt][nt], al0, al1, al2, al3, bh0, bh1);
                }
            }
        }
        __syncthreads();
    }

    // Epilogue: bias + tanh
#pragma unroll
    for (int mt = 0; mt < 2; mt++) {
#pragma unroll
        for (int nt = 0; nt < 4; nt++) {
            const int row = m0 + warpM + mt * 16 + gid;
            const int col = n0 + warpN + nt * 8 + tig * 2;
            float2 bv = *reinterpret_cast<const float2*>(bias + col);
            float2 o0;
            o0.x = tanhf(acc[mt][nt][0] + bv.x);
            o0.y = tanhf(acc[mt][nt][1] + bv.y);
            *reinterpret_cast<float2*>(C + (size_t)row * N + col) = o0;
            float2 o1;
            o1.x = tanhf(acc[mt][nt][2] + bv.x);
            o1.y = tanhf(acc[mt][nt][3] + bv.y);
            *reinterpret_cast<float2*>(C + (size_t)(row + 8) * N + col) = o1;
        }
    }
}

// ---------------------------------------------------------------------------
// Launch
// ---------------------------------------------------------------------------
extern "C" void kernel_launch(void* const* d_in, const int* in_sizes, int n_in,
                              void* d_out, int out_size)
{
    const float* token_embeds = (const float*)d_in[0];
    const int*   attn_mask    = (const int*)  d_in[1];
    const float* W1           = (const float*)d_in[2];
    const float* b1           = (const float*)d_in[3];
    const float* W2           = (const float*)d_in[4];
    const float* b2           = (const float*)d_in[5];
    float*       out          = (float*)d_out;

    float* pooled = nullptr;
    float* hidden = nullptr;
    cudaGetSymbolAddress((void**)&pooled, g_pooled);
    cudaGetSymbolAddress((void**)&hidden, g_hidden);

    // 1) masked sum pooling
    pool_kernel<<<BATCH, 384>>>(token_embeds, attn_mask);

    // 2) h = tanh(pooled @ W1 + b1)
    dim3 grid1(DIM / BN, BATCH / BM);   // (12, 16) = 192 blocks
    gemm_tf32_bias_tanh<<<grid1, 128>>>(pooled, W1, b1, hidden, BATCH, DIM, DIM);

    // 3) out = tanh(h @ W2 + b2)
    gemm_tf32_bias_tanh<<<grid1, 128>>>(hidden, W2, b2, out, BATCH, DIM, DIM);
}

// round 5
// speedup vs baseline: 1.2613x; 1.2613x over previous
#include <cuda_runtime.h>
#include <cuda_bf16.h>
#include <math.h>
#include <stdint.h>

// Problem dims (fixed by the dataset)
#define BATCH 1024
#define SEQ   512
#define DIM   768

// Scratch (allocation-free rule: __device__ globals)
__device__ float g_pooled[BATCH * DIM];
__device__ float g_hidden[BATCH * DIM];

// ---------------------------------------------------------------------------
// Kernel 1: masked sum pooling (at DRAM roofline; streaming loads)
// ---------------------------------------------------------------------------
__device__ __forceinline__ float2 ldcs_f2(const float2* p)
{
    float2 v;
    asm volatile("ld.global.cs.v2.f32 {%0,%1}, [%2];"
                 : "=f"(v.x), "=f"(v.y) : "l"(p));
    return v;
}

__global__ __launch_bounds__(384) void pool_kernel(
    const float* __restrict__ x,      // [BATCH, SEQ, DIM]
    const int*   __restrict__ mask)   // [BATCH, SEQ]
{
    __shared__ int s_idx[SEQ];
    __shared__ int s_cnt;

    const int b   = blockIdx.x;
    const int tid = threadIdx.x;

    if (tid == 0) s_cnt = 0;
    __syncthreads();

    const int* mrow = mask + (size_t)b * SEQ;
    for (int s = tid; s < SEQ; s += 384) {
        if (mrow[s] != 0) {
            int p = atomicAdd(&s_cnt, 1);
            s_idx[p] = s;
        }
    }
    __syncthreads();

    const int cnt = s_cnt;
    const float2* base = reinterpret_cast<const float2*>(x + (size_t)b * SEQ * DIM);
    const int rs2 = DIM / 2;

    float2 acc; acc.x = 0.f; acc.y = 0.f;

    int i = 0;
    for (; i + 4 <= cnt; i += 4) {
        int s0 = s_idx[i + 0];
        int s1 = s_idx[i + 1];
        int s2 = s_idx[i + 2];
        int s3 = s_idx[i + 3];
        float2 v0 = ldcs_f2(base + (size_t)s0 * rs2 + tid);
        float2 v1 = ldcs_f2(base + (size_t)s1 * rs2 + tid);
        float2 v2 = ldcs_f2(base + (size_t)s2 * rs2 + tid);
        float2 v3 = ldcs_f2(base + (size_t)s3 * rs2 + tid);
        acc.x += (v0.x + v1.x) + (v2.x + v3.x);
        acc.y += (v0.y + v1.y) + (v2.y + v3.y);
    }
    for (; i < cnt; i++) {
        float2 v = ldcs_f2(base + (size_t)s_idx[i] * rs2 + tid);
        acc.x += v.x;
        acc.y += v.y;
    }

    reinterpret_cast<float2*>(g_pooled + (size_t)b * DIM)[tid] = acc;
}

// ---------------------------------------------------------------------------
// Kernel 2: C = tanh(A @ B + bias), error-compensated bf16 tensor-core GEMM.
// mma.sync.m16n8k16.bf16 with hi/lo split (3 terms: HH + HL + LH).
// Split once at tile-store; smem holds bf16x2 K-pairs -> half of R2's LDS
// bytes AND half its MMA instruction count. Zero inner-loop ALU.
// Geometry: BM=BN=64, BK=32, 128 threads (2x2 warps, 32x32 warp tiles),
// grid 192 blocks -> multiple CTAs/SM for latency hiding.
// ---------------------------------------------------------------------------
#define BM 64
#define BN 64
#define BK 32
#define KP 16          // K-pairs per tile (BK/2)
#define SSTR 72        // smem row stride in u32: tig*8+gid conflict-free

__device__ __forceinline__ void split_bf(float x, float& h, float& l)
{
    __nv_bfloat16 hb = __float2bfloat16(x);
    h = __bfloat162float(hb);
    l = x - h;
}

__device__ __forceinline__ uint32_t bf2_pack(float lo_k, float hi_k)
{
    __nv_bfloat162 t = __floats2bfloat162_rn(lo_k, hi_k);  // .x = lo_k (low bits)
    return *reinterpret_cast<uint32_t*>(&t);
}

__device__ __forceinline__ void mma_bf16(
    float c[4], uint32_t a0, uint32_t a1, uint32_t a2, uint32_t a3,
    uint32_t b0, uint32_t b1)
{
    asm volatile(
        "mma.sync.aligned.m16n8k16.row.col.f32.bf16.bf16.f32 "
        "{%0,%1,%2,%3}, {%4,%5,%6,%7}, {%8,%9}, {%0,%1,%2,%3};\n"
        : "+f"(c[0]), "+f"(c[1]), "+f"(c[2]), "+f"(c[3])
        : "r"(a0), "r"(a1), "r"(a2), "r"(a3), "r"(b0), "r"(b1));
}

__global__ __launch_bounds__(128) void gemm_bf16_bias_tanh(
    const float* __restrict__ A,
    const float* __restrict__ Bm,
    const float* __restrict__ bias,
    float* __restrict__ C,
    int M, int N, int K)
{
    // [k-pair][m or n], u32 = bf16x2 (k even in low half)
    __shared__ uint32_t Ah[KP][SSTR], Al[KP][SSTR];
    __shared__ uint32_t Bh[KP][SSTR], Bl[KP][SSTR];

    const int tid  = threadIdx.x;
    const int lane = tid & 31;
    const int warp = tid >> 5;       // 0..3
    const int gid  = lane >> 2;      // 0..7
    const int tig  = lane & 3;       // 0..3
    const int warpM = (warp & 1) * 32;
    const int warpN = (warp >> 1) * 32;

    const int m0 = blockIdx.y * BM;
    const int n0 = blockIdx.x * BN;

    float acc[2][4][4];
#pragma unroll
    for (int mt = 0; mt < 2; mt++)
#pragma unroll
        for (int nt = 0; nt < 4; nt++)
#pragma unroll
            for (int r = 0; r < 4; r++)
                acc[mt][nt][r] = 0.f;

    // A load mapping: 64m x 32k floats = 512 float4, 4/thread
    const int a_ar = tid >> 3;          // 0..15 (+16*l) -> m row... (id>>3)
    // B task mapping handled inline.

    for (int k0 = 0; k0 < K; k0 += BK) {
        // --- A tile: split + pack k-pairs, store transposed ---
#pragma unroll
        for (int l = 0; l < 4; l++) {
            int id = tid + l * 128;          // 0..511
            int ar = id >> 3;                // 0..63 (m)
            int ac = (id & 7) << 2;          // 0..28 (k)
            float4 v = *reinterpret_cast<const float4*>(
                A + (size_t)(m0 + ar) * K + k0 + ac);
            float hx, lx, hy, ly, hz, lz, hw, lw;
            split_bf(v.x, hx, lx); split_bf(v.y, hy, ly);
            split_bf(v.z, hz, lz); split_bf(v.w, hw, lw);
            int kp = ac >> 1;                // 0..14 even
            Ah[kp    ][ar] = bf2_pack(hx, hy);
            Ah[kp + 1][ar] = bf2_pack(hz, hw);
            Al[kp    ][ar] = bf2_pack(lx, ly);
            Al[kp + 1][ar] = bf2_pack(lz, lw);
        }
        // --- B tile: combine row-pairs (k, k+1) into bf16x2 per column ---
#pragma unroll
        for (int l = 0; l < 2; l++) {
            int t  = tid + l * 128;          // 0..255
            int kp = t >> 4;                 // 0..15
            int bc = (t & 15) << 2;          // 0..60
            const float* r0 = Bm + (size_t)(k0 + 2 * kp    ) * N + n0 + bc;
            const float* r1 = Bm + (size_t)(k0 + 2 * kp + 1) * N + n0 + bc;
            float4 v0 = *reinterpret_cast<const float4*>(r0);
            float4 v1 = *reinterpret_cast<const float4*>(r1);
            float h0, l0r, h1, l1r;
#pragma unroll
            for (int j = 0; j < 4; j++) {
                float e0 = (&v0.x)[j];
                float e1 = (&v1.x)[j];
                split_bf(e0, h0, l0r);
                split_bf(e1, h1, l1r);
                Bh[kp][bc + j] = bf2_pack(h0, h1);
                Bl[kp][bc + j] = bf2_pack(l0r, l1r);
            }
        }
        __syncthreads();

        // Two m16n8k16 K-steps cover the 16 k-pairs
#pragma unroll
        for (int ks = 0; ks < 2; ks++) {
            const int kb = ks * 8;           // pair offset

            uint32_t ah[2][4], al[2][4];
#pragma unroll
            for (int mt = 0; mt < 2; mt++) {
                const int rm = warpM + mt * 16 + gid;
                ah[mt][0] = Ah[kb + tig    ][rm    ];
                ah[mt][1] = Ah[kb + tig    ][rm + 8];
                ah[mt][2] = Ah[kb + tig + 4][rm    ];
                ah[mt][3] = Ah[kb + tig + 4][rm + 8];
                al[mt][0] = Al[kb + tig    ][rm    ];
                al[mt][1] = Al[kb + tig    ][rm + 8];
                al[mt][2] = Al[kb + tig + 4][rm    ];
                al[mt][3] = Al[kb + tig + 4][rm + 8];
            }
            uint32_t bh[4][2], bl[4][2];
#pragma unroll
            for (int nt = 0; nt < 4; nt++) {
                const int nn = warpN + nt * 8 + gid;
                bh[nt][0] = Bh[kb + tig    ][nn];
                bh[nt][1] = Bh[kb + tig + 4][nn];
                bl[nt][0] = Bl[kb + tig    ][nn];
                bl[nt][1] = Bl[kb + tig + 4][nn];
            }

#pragma unroll
            for (int mt = 0; mt < 2; mt++)
#pragma unroll
                for (int nt = 0; nt < 4; nt++) {
                    mma_bf16(acc[mt][nt], ah[mt][0], ah[mt][1], ah[mt][2], ah[mt][3],
                             bh[nt][0], bh[nt][1]);
                    mma_bf16(acc[mt][nt], ah[mt][0], ah[mt][1], ah[mt][2], ah[mt][3],
                             bl[nt][0], bl[nt][1]);
                    mma_bf16(acc[mt][nt], al[mt][0], al[mt][1], al[mt][2], al[mt][3],
                             bh[nt][0], bh[nt][1]);
                }
        }
        __syncthreads();
    }

    // Epilogue: bias + tanh (same fragment layout as m16n8k8)
#pragma unroll
    for (int mt = 0; mt < 2; mt++) {
#pragma unroll
        for (int nt = 0; nt < 4; nt++) {
            const int row = m0 + warpM + mt * 16 + gid;
            const int col = n0 + warpN + nt * 8 + tig * 2;
            float2 bv = *reinterpret_cast<const float2*>(bias + col);
            float2 o0;
            o0.x = tanhf(acc[mt][nt][0] + bv.x);
            o0.y = tanhf(acc[mt][nt][1] + bv.y);
            *reinterpret_cast<float2*>(C + (size_t)row * N + col) = o0;
            float2 o1;
            o1.x = tanhf(acc[mt][nt][2] + bv.x);
            o1.y = tanhf(acc[mt][nt][3] + bv.y);
            *reinterpret_cast<float2*>(C + (size_t)(row + 8) * N + col) = o1;
        }
    }
}

// ---------------------------------------------------------------------------
// Launch
// ---------------------------------------------------------------------------
extern "C" void kernel_launch(void* const* d_in, const int* in_sizes, int n_in,
                              void* d_out, int out_size)
{
    const float* token_embeds = (const float*)d_in[0];
    const int*   attn_mask    = (const int*)  d_in[1];
    const float* W1           = (const float*)d_in[2];
    const float* b1           = (const float*)d_in[3];
    const float* W2           = (const float*)d_in[4];
    const float* b2           = (const float*)d_in[5];
    float*       out          = (float*)d_out;

    float* pooled = nullptr;
    float* hidden = nullptr;
    cudaGetSymbolAddress((void**)&pooled, g_pooled);
    cudaGetSymbolAddress((void**)&hidden, g_hidden);

    // 1) masked sum pooling
    pool_kernel<<<BATCH, 384>>>(token_embeds, attn_mask);

    // 2) h = tanh(pooled @ W1 + b1)
    dim3 grid1(DIM / BN, BATCH / BM);   // (12, 16) = 192 blocks
    gemm_bf16_bias_tanh<<<grid1, 128>>>(pooled, W1, b1, hidden, BATCH, DIM, DIM);

    // 3) out = tanh(h @ W2 + b2)
    gemm_bf16_bias_tanh<<<grid1, 128>>>(hidden, W2, b2, out, BATCH, DIM, DIM);
}

// round 7
// speedup vs baseline: 1.6164x; 1.2815x over previous
#include <cuda_runtime.h>
#include <cuda_bf16.h>
#include <math.h>
#include <stdint.h>

// Problem dims (fixed by the dataset)
#define BATCH 1024
#define SEQ   512
#define DIM   768

// ---------------------------------------------------------------------------
// Scratch (allocation-free rule: __device__ globals)
// Packed bf16x2 (hi/lo split) operands, k-contiguous everywhere.
// ---------------------------------------------------------------------------
__device__ uint32_t g_pool_hi[BATCH * DIM / 2];
__device__ uint32_t g_pool_lo[BATCH * DIM / 2];
__device__ uint32_t g_hid_hi[BATCH * DIM / 2];
__device__ uint32_t g_hid_lo[BATCH * DIM / 2];
__device__ __nv_bfloat16 g_w1t_hi[DIM * DIM];   // [N][K] (transposed W1)
__device__ __nv_bfloat16 g_w1t_lo[DIM * DIM];
__device__ __nv_bfloat16 g_w2t_hi[DIM * DIM];
__device__ __nv_bfloat16 g_w2t_lo[DIM * DIM];

__device__ __forceinline__ void split1(float x, float& h, float& l)
{
    __nv_bfloat16 hb = __float2bfloat16(x);
    h = __bfloat162float(hb);
    l = x - h;
}

__device__ __forceinline__ uint32_t pack_bf2(float a, float b)
{
    __nv_bfloat162 t = __floats2bfloat162_rn(a, b);   // .x = a (low 16 bits)
    return *reinterpret_cast<uint32_t*>(&t);
}

// ---------------------------------------------------------------------------
// Kernel 1: masked sum pooling -> bf16 hi/lo output (DRAM-roofline bound)
// ---------------------------------------------------------------------------
__device__ __forceinline__ float2 ldcs_f2(const float2* p)
{
    float2 v;
    asm volatile("ld.global.cs.v2.f32 {%0,%1}, [%2];"
                 : "=f"(v.x), "=f"(v.y) : "l"(p));
    return v;
}

__global__ __launch_bounds__(384) void pool_kernel(
    const float* __restrict__ x,      // [BATCH, SEQ, DIM]
    const int*   __restrict__ mask)   // [BATCH, SEQ]
{
    __shared__ int s_idx[SEQ];
    __shared__ int s_cnt;

    const int b   = blockIdx.x;
    const int tid = threadIdx.x;

    if (tid == 0) s_cnt = 0;
    __syncthreads();

    const int* mrow = mask + (size_t)b * SEQ;
    for (int s = tid; s < SEQ; s += 384) {
        if (mrow[s] != 0) {
            int p = atomicAdd(&s_cnt, 1);
            s_idx[p] = s;
        }
    }
    __syncthreads();

    const int cnt = s_cnt;
    const float2* base = reinterpret_cast<const float2*>(x + (size_t)b * SEQ * DIM);
    const int rs2 = DIM / 2;

    float2 acc; acc.x = 0.f; acc.y = 0.f;

    int i = 0;
    for (; i + 4 <= cnt; i += 4) {
        int s0 = s_idx[i + 0];
        int s1 = s_idx[i + 1];
        int s2 = s_idx[i + 2];
        int s3 = s_idx[i + 3];
        float2 v0 = ldcs_f2(base + (size_t)s0 * rs2 + tid);
        float2 v1 = ldcs_f2(base + (size_t)s1 * rs2 + tid);
        float2 v2 = ldcs_f2(base + (size_t)s2 * rs2 + tid);
        float2 v3 = ldcs_f2(base + (size_t)s3 * rs2 + tid);
        acc.x += (v0.x + v1.x) + (v2.x + v3.x);
        acc.y += (v0.y + v1.y) + (v2.y + v3.y);
    }
    for (; i < cnt; i++) {
        float2 v = ldcs_f2(base + (size_t)s_idx[i] * rs2 + tid);
        acc.x += v.x;
        acc.y += v.y;
    }

    float hx, lx, hy, ly;
    split1(acc.x, hx, lx);
    split1(acc.y, hy, ly);
    g_pool_hi[(size_t)b * rs2 + tid] = pack_bf2(hx, hy);
    g_pool_lo[(size_t)b * rs2 + tid] = pack_bf2(lx, ly);
}

// ---------------------------------------------------------------------------
// Kernel 1b: W [K][N] fp32 -> Wt [N][K] bf16 hi/lo (tiled transpose)
// grid (24, 24, 2), block (32, 8)
// ---------------------------------------------------------------------------
__global__ __launch_bounds__(256) void convert_w_kernel(
    const float* __restrict__ W1, const float* __restrict__ W2)
{
    __shared__ float t[32][33];
    const float* W = blockIdx.z ? W2 : W1;
    __nv_bfloat16* Oh = blockIdx.z ? g_w2t_hi : g_w1t_hi;
    __nv_bfloat16* Ol = blockIdx.z ? g_w2t_lo : g_w1t_lo;

    const int n0 = blockIdx.x * 32;
    const int k0 = blockIdx.y * 32;
    const int tx = threadIdx.x;
    const int ty = threadIdx.y;

#pragma unroll
    for (int i = 0; i < 4; i++)
        t[ty + 8 * i][tx] = W[(size_t)(k0 + ty + 8 * i) * DIM + n0 + tx];
    __syncthreads();

#pragma unroll
    for (int i = 0; i < 4; i++) {
        int r = ty + 8 * i;                 // local n
        float v = t[tx][r];                 // = W[k0+tx][n0+r]
        float h, l;
        split1(v, h, l);
        size_t o = (size_t)(n0 + r) * DIM + k0 + tx;
        Oh[o] = __float2bfloat16(h);
        Ol[o] = __float2bfloat16(l);        // l fits bf16 exactly enough
    }
}

// ---------------------------------------------------------------------------
// Kernel 2: C = tanh(A @ B^T + bias); A [M][K] bf16 hi/lo (packed u32 pairs),
// B [N][K] bf16 hi/lo. 3-term split: D = Ah*Bh + Ah*Bl + Al*Bh.
// cp.async 3-stage pipeline; BM=BN=64, BK=32; 128 threads (2x2 warps).
// smem tiles [row][kp u32] with 80B row stride (conflict-free frags).
// ---------------------------------------------------------------------------
#define SROW 80
#define TILE_B (64 * SROW)            // 5120 B per operand tile
#define STAGE_B (4 * TILE_B)          // 20480 B
#define NSTAGES 3
#define GEMM_SMEM (NSTAGES * STAGE_B) // 61440 B
#define OFF_AH 0
#define OFF_AL TILE_B
#define OFF_BH (2 * TILE_B)
#define OFF_BL (3 * TILE_B)

__device__ __forceinline__ void cp16(uint32_t dst, const void* src)
{
    asm volatile("cp.async.cg.shared.global [%0], [%1], 16;"
                 :: "r"(dst), "l"(src));
}
#define CP_COMMIT() asm volatile("cp.async.commit_group;" ::: "memory")
#define CP_WAIT2()  asm volatile("cp.async.wait_group 2;" ::: "memory")

__device__ __forceinline__ void mma_bf16(
    float c[4], uint32_t a0, uint32_t a1, uint32_t a2, uint32_t a3,
    uint32_t b0, uint32_t b1)
{
    asm volatile(
        "mma.sync.aligned.m16n8k16.row.col.f32.bf16.bf16.f32 "
        "{%0,%1,%2,%3}, {%4,%5,%6,%7}, {%8,%9}, {%0,%1,%2,%3};\n"
        : "+f"(c[0]), "+f"(c[1]), "+f"(c[2]), "+f"(c[3])
        : "r"(a0), "r"(a1), "r"(a2), "r"(a3), "r"(b0), "r"(b1));
}

template <bool SPLIT_OUT>
__global__ __launch_bounds__(128) void gemm_pipe(
    const __nv_bfloat16* __restrict__ Ah,  // [M][K]
    const __nv_bfloat16* __restrict__ Al,
    const __nv_bfloat16* __restrict__ Bh,  // [N][K]
    const __nv_bfloat16* __restrict__ Bl,
    const float* __restrict__ bias,
    float* __restrict__ Cf,                 // if !SPLIT_OUT
    uint32_t* __restrict__ Chh,             // if SPLIT_OUT
    uint32_t* __restrict__ Chl,
    int M, int N, int K)
{
    extern __shared__ char dyn[];
    const uint32_t sbase = (uint32_t)__cvta_generic_to_shared(dyn);

    const int tid  = threadIdx.x;
    const int lane = tid & 31;
    const int warp = tid >> 5;       // 0..3
    const int gid  = lane >> 2;      // 0..7
    const int tig  = lane & 3;       // 0..3
    const int warpM = (warp & 1) * 32;
    const int warpN = (warp >> 1) * 32;

    const int m0 = blockIdx.y * 64;
    const int n0 = blockIdx.x * 64;

    // cp.async chunk mapping: 256 chunks per 64x32 tile; 2 per thread.
    const int r0 = tid >> 2;          // row for l=0: 0..31
    const int q0 = tid & 3;           // 16B col group (k 8q..8q+7)

    float acc[2][4][4];
#pragma unroll
    for (int mt = 0; mt < 2; mt++)
#pragma unroll
        for (int nt = 0; nt < 4; nt++)
#pragma unroll
            for (int r = 0; r < 4; r++)
                acc[mt][nt][r] = 0.f;

#define ISSUE(k0v, st)                                                         \
    do {                                                                       \
        uint32_t sb = sbase + (st) * STAGE_B;                                  \
        _Pragma("unroll")                                                      \
        for (int l = 0; l < 2; l++) {                                          \
            int row = r0 + 32 * l;                                             \
            uint32_t d = sb + row * SROW + q0 * 16;                            \
            size_t ga = (size_t)(m0 + row) * K + (k0v) + q0 * 8;               \
            size_t gb = (size_t)(n0 + row) * K + (k0v) + q0 * 8;               \
            cp16(d + OFF_AH, Ah + ga);                                         \
            cp16(d + OFF_AL, Al + ga);                                         \
            cp16(d + OFF_BH, Bh + gb);                                         \
            cp16(d + OFF_BL, Bl + gb);                                         \
        }                                                                      \
        CP_COMMIT();                                                           \
    } while (0)

#define LD32(off) (*reinterpret_cast<const uint32_t*>(dyn + (off)))

    // Prologue: fill 3 stages
    ISSUE(0, 0);
    ISSUE(32, 1);
    ISSUE(64, 2);

    const int NIT = K / 32;   // 24
    for (int t = 0; t < NIT; t++) {
        CP_WAIT2();
        __syncthreads();

        const uint32_t sb = (uint32_t)((t % NSTAGES) * STAGE_B);
#pragma unroll
        for (int ks = 0; ks < 2; ks++) {
            const int kb = ks * 8;     // k-pair offset

            uint32_t ah[2][4], al[2][4];
#pragma unroll
            for (int mt = 0; mt < 2; mt++) {
                const int rm = warpM + mt * 16 + gid;
                uint32_t b0 = sb + rm * SROW + (kb + tig) * 4;
                uint32_t b8 = sb + (rm + 8) * SROW + (kb + tig) * 4;
                ah[mt][0] = LD32(b0 + OFF_AH);
                ah[mt][1] = LD32(b8 + OFF_AH);
                ah[mt][2] = LD32(b0 + OFF_AH + 16);
                ah[mt][3] = LD32(b8 + OFF_AH + 16);
                al[mt][0] = LD32(b0 + OFF_AL);
                al[mt][1] = LD32(b8 + OFF_AL);
                al[mt][2] = LD32(b0 + OFF_AL + 16);
                al[mt][3] = LD32(b8 + OFF_AL + 16);
            }
            uint32_t bh[4][2], bl[4][2];
#pragma unroll
            for (int nt = 0; nt < 4; nt++) {
                const int nn = warpN + nt * 8 + gid;
                uint32_t b0 = sb + nn * SROW + (kb + tig) * 4;
                bh[nt][0] = LD32(b0 + OFF_BH);
                bh[nt][1] = LD32(b0 + OFF_BH + 16);
                bl[nt][0] = LD32(b0 + OFF_BL);
                bl[nt][1] = LD32(b0 + OFF_BL + 16);
            }

#pragma unroll
            for (int mt = 0; mt < 2; mt++)
#pragma unroll
                for (int nt = 0; nt < 4; nt++) {
                    mma_bf16(acc[mt][nt], ah[mt][0], ah[mt][1], ah[mt][2], ah[mt][3],
                             bh[nt][0], bh[nt][1]);
                    mma_bf16(acc[mt][nt], ah[mt][0], ah[mt][1], ah[mt][2], ah[mt][3],
                             bl[nt][0], bl[nt][1]);
                    mma_bf16(acc[mt][nt], al[mt][0], al[mt][1], al[mt][2], al[mt][3],
                             bh[nt][0], bh[nt][1]);
                }
        }
        __syncthreads();

        if (t + NSTAGES < NIT) {
            ISSUE((t + NSTAGES) * 32, t % NSTAGES);
        } else {
            CP_COMMIT();   // keep group count uniform
        }
    }

    // Epilogue: bias + tanh
#pragma unroll
    for (int mt = 0; mt < 2; mt++) {
#pragma unroll
        for (int nt = 0; nt < 4; nt++) {
            const int row = m0 + warpM + mt * 16 + gid;
            const int col = n0 + warpN + nt * 8 + tig * 2;
            float2 bv = *reinterpret_cast<const float2*>(bias + col);
            float o0 = tanhf(acc[mt][nt][0] + bv.x);
            float o1 = tanhf(acc[mt][nt][1] + bv.y);
            float o2 = tanhf(acc[mt][nt][2] + bv.x);
            float o3 = tanhf(acc[mt][nt][3] + bv.y);
            if (SPLIT_OUT) {
                float h0, l0, h1, l1;
                split1(o0, h0, l0);
                split1(o1, h1, l1);
                size_t idx = ((size_t)row * N + col) >> 1;
                Chh[idx] = pack_bf2(h0, h1);
                Chl[idx] = pack_bf2(l0, l1);
                split1(o2, h0, l0);
                split1(o3, h1, l1);
                size_t idx2 = ((size_t)(row + 8) * N + col) >> 1;
                Chh[idx2] = pack_bf2(h0, h1);
                Chl[idx2] = pack_bf2(l0, l1);
            } else {
                float2 w0; w0.x = o0; w0.y = o1;
                *reinterpret_cast<float2*>(Cf + (size_t)row * N + col) = w0;
                float2 w1; w1.x = o2; w1.y = o3;
                *reinterpret_cast<float2*>(Cf + (size_t)(row + 8) * N + col) = w1;
            }
        }
    }
#undef ISSUE
#undef LD32
}

// ---------------------------------------------------------------------------
// Launch
// ---------------------------------------------------------------------------
extern "C" void kernel_launch(void* const* d_in, const int* in_sizes, int n_in,
                              void* d_out, int out_size)
{
    const float* token_embeds = (const float*)d_in[0];
    const int*   attn_mask    = (const int*)  d_in[1];
    const float* W1           = (const float*)d_in[2];
    const float* b1           = (const float*)d_in[3];
    const float* W2           = (const float*)d_in[4];
    const float* b2           = (const float*)d_in[5];
    float*       out          = (float*)d_out;

    void *p_ph, *p_pl, *p_hh, *p_hl, *p_w1h, *p_w1l, *p_w2h, *p_w2l;
    cudaGetSymbolAddress(&p_ph,  g_pool_hi);
    cudaGetSymbolAddress(&p_pl,  g_pool_lo);
    cudaGetSymbolAddress(&p_hh,  g_hid_hi);
    cudaGetSymbolAddress(&p_hl,  g_hid_lo);
    cudaGetSymbolAddress(&p_w1h, g_w1t_hi);
    cudaGetSymbolAddress(&p_w1l, g_w1t_lo);
    cudaGetSymbolAddress(&p_w2h, g_w2t_hi);
    cudaGetSymbolAddress(&p_w2l, g_w2t_lo);

    cudaFuncSetAttribute(gemm_pipe<true>,
                         cudaFuncAttributeMaxDynamicSharedMemorySize, GEMM_SMEM);
    cudaFuncSetAttribute(gemm_pipe<false>,
                         cudaFuncAttributeMaxDynamicSharedMemorySize, GEMM_SMEM);

    // 1) masked sum pooling -> bf16 hi/lo
    pool_kernel<<<BATCH, 384>>>(token_embeds, attn_mask);

    // 1b) weight transpose + split (independent of pool; serial stream is fine)
    dim3 cgrid(DIM / 32, DIM / 32, 2);
    convert_w_kernel<<<cgrid, dim3(32, 8)>>>(W1, W2);

    // 2) hidden = tanh(pooled @ W1 + b1) -> bf16 hi/lo
    dim3 grid1(DIM / 64, BATCH / 64);   // (12, 16) = 192 blocks
    gemm_pipe<true><<<grid1, 128, GEMM_SMEM>>>(
        (const __nv_bfloat16*)p_ph, (const __nv_bfloat16*)p_pl,
        (const __nv_bfloat16*)p_w1h, (const __nv_bfloat16*)p_w1l,
        b1, nullptr, (uint32_t*)p_hh, (uint32_t*)p_hl, BATCH, DIM, DIM);

    // 3) out = tanh(hidden @ W2 + b2) -> fp32
    gemm_pipe<false><<<grid1, 128, GEMM_SMEM>>>(
        (const __nv_bfloat16*)p_hh, (const __nv_bfloat16*)p_hl,
        (const __nv_bfloat16*)p_w2h, (const __nv_bfloat16*)p_w2l,
        b2, out, nullptr, nullptr, BATCH, DIM, DIM);
}

// round 8
// speedup vs baseline: 1.6291x; 1.0079x over previous
#include <cuda_runtime.h>
#include <cuda_bf16.h>
#include <math.h>
#include <stdint.h>

// Problem dims (fixed by the dataset)
#define BATCH 1024
#define SEQ   512
#define DIM   768

// ---------------------------------------------------------------------------
// Scratch (allocation-free rule: __device__ globals)
// Packed bf16x2 (hi/lo split) operands, k-contiguous everywhere.
// ---------------------------------------------------------------------------
__device__ uint32_t g_pool_hi[BATCH * DIM / 2];
__device__ uint32_t g_pool_lo[BATCH * DIM / 2];
__device__ uint32_t g_hid_hi[BATCH * DIM / 2];
__device__ uint32_t g_hid_lo[BATCH * DIM / 2];
__device__ __nv_bfloat16 g_w1t_hi[DIM * DIM];   // [N][K] (transposed W1)
__device__ __nv_bfloat16 g_w1t_lo[DIM * DIM];
__device__ __nv_bfloat16 g_w2t_hi[DIM * DIM];
__device__ __nv_bfloat16 g_w2t_lo[DIM * DIM];

__device__ __forceinline__ void split1(float x, float& h, float& l)
{
    __nv_bfloat16 hb = __float2bfloat16(x);
    h = __bfloat162float(hb);
    l = x - h;
}

__device__ __forceinline__ uint32_t pack_bf2(float a, float b)
{
    __nv_bfloat162 t = __floats2bfloat162_rn(a, b);   // .x = a (low 16 bits)
    return *reinterpret_cast<uint32_t*>(&t);
}

// ---------------------------------------------------------------------------
// Kernel 1: masked sum pooling -> bf16 hi/lo output (DRAM-roofline bound)
// ---------------------------------------------------------------------------
__device__ __forceinline__ float2 ldcs_f2(const float2* p)
{
    float2 v;
    asm volatile("ld.global.cs.v2.f32 {%0,%1}, [%2];"
                 : "=f"(v.x), "=f"(v.y) : "l"(p));
    return v;
}

__global__ __launch_bounds__(384) void pool_kernel(
    const float* __restrict__ x,      // [BATCH, SEQ, DIM]
    const int*   __restrict__ mask)   // [BATCH, SEQ]
{
    __shared__ int s_idx[SEQ];
    __shared__ int s_cnt;

    const int b   = blockIdx.x;
    const int tid = threadIdx.x;

    if (tid == 0) s_cnt = 0;
    __syncthreads();

    const int* mrow = mask + (size_t)b * SEQ;
    for (int s = tid; s < SEQ; s += 384) {
        if (mrow[s] != 0) {
            int p = atomicAdd(&s_cnt, 1);
            s_idx[p] = s;
        }
    }
    __syncthreads();

    const int cnt = s_cnt;
    const float2* base = reinterpret_cast<const float2*>(x + (size_t)b * SEQ * DIM);
    const int rs2 = DIM / 2;

    float2 acc; acc.x = 0.f; acc.y = 0.f;

    int i = 0;
    for (; i + 4 <= cnt; i += 4) {
        int s0 = s_idx[i + 0];
        int s1 = s_idx[i + 1];
        int s2 = s_idx[i + 2];
        int s3 = s_idx[i + 3];
        float2 v0 = ldcs_f2(base + (size_t)s0 * rs2 + tid);
        float2 v1 = ldcs_f2(base + (size_t)s1 * rs2 + tid);
        float2 v2 = ldcs_f2(base + (size_t)s2 * rs2 + tid);
        float2 v3 = ldcs_f2(base + (size_t)s3 * rs2 + tid);
        acc.x += (v0.x + v1.x) + (v2.x + v3.x);
        acc.y += (v0.y + v1.y) + (v2.y + v3.y);
    }
    for (; i < cnt; i++) {
        float2 v = ldcs_f2(base + (size_t)s_idx[i] * rs2 + tid);
        acc.x += v.x;
        acc.y += v.y;
    }

    float hx, lx, hy, ly;
    split1(acc.x, hx, lx);
    split1(acc.y, hy, ly);
    g_pool_hi[(size_t)b * rs2 + tid] = pack_bf2(hx, hy);
    g_pool_lo[(size_t)b * rs2 + tid] = pack_bf2(lx, ly);
}

// ---------------------------------------------------------------------------
// Kernel 1b: W [K][N] fp32 -> Wt [N][K] bf16 hi/lo (tiled transpose)
// grid (24, 24, 2), block (32, 8)
// ---------------------------------------------------------------------------
__global__ __launch_bounds__(256) void convert_w_kernel(
    const float* __restrict__ W1, const float* __restrict__ W2)
{
    __shared__ float t[32][33];
    const float* W = blockIdx.z ? W2 : W1;
    __nv_bfloat16* Oh = blockIdx.z ? g_w2t_hi : g_w1t_hi;
    __nv_bfloat16* Ol = blockIdx.z ? g_w2t_lo : g_w1t_lo;

    const int n0 = blockIdx.x * 32;
    const int k0 = blockIdx.y * 32;
    const int tx = threadIdx.x;
    const int ty = threadIdx.y;

#pragma unroll
    for (int i = 0; i < 4; i++)
        t[ty + 8 * i][tx] = W[(size_t)(k0 + ty + 8 * i) * DIM + n0 + tx];
    __syncthreads();

#pragma unroll
    for (int i = 0; i < 4; i++) {
        int r = ty + 8 * i;                 // local n
        float v = t[tx][r];                 // = W[k0+tx][n0+r]
        float h, l;
        split1(v, h, l);
        size_t o = (size_t)(n0 + r) * DIM + k0 + tx;
        Oh[o] = __float2bfloat16(h);
        Ol[o] = __float2bfloat16(l);        // l fits bf16 exactly enough
    }
}

// ---------------------------------------------------------------------------
// Kernel 2: C = tanh(A @ B^T + bias); A [M][K] bf16 hi/lo (packed u32 pairs),
// B [N][K] bf16 hi/lo. 3-term split: D = Ah*Bh + Ah*Bl + Al*Bh.
// cp.async 3-stage pipeline; BM=BN=64, BK=32; 128 threads (2x2 warps).
// smem tiles [row][kp u32] with 80B row stride (conflict-free frags).
// ---------------------------------------------------------------------------
#define SROW 80
#define TILE_B (64 * SROW)            // 5120 B per operand tile
#define STAGE_B (4 * TILE_B)          // 20480 B
#define NSTAGES 3
#define GEMM_SMEM (NSTAGES * STAGE_B) // 61440 B
#define OFF_AH 0
#define OFF_AL TILE_B
#define OFF_BH (2 * TILE_B)
#define OFF_BL (3 * TILE_B)

__device__ __forceinline__ void cp16(uint32_t dst, const void* src)
{
    asm volatile("cp.async.cg.shared.global [%0], [%1], 16;"
                 :: "r"(dst), "l"(src));
}
#define CP_COMMIT() asm volatile("cp.async.commit_group;" ::: "memory")
#define CP_WAIT2()  asm volatile("cp.async.wait_group 2;" ::: "memory")

__device__ __forceinline__ void mma_bf16(
    float c[4], uint32_t a0, uint32_t a1, uint32_t a2, uint32_t a3,
    uint32_t b0, uint32_t b1)
{
    asm volatile(
        "mma.sync.aligned.m16n8k16.row.col.f32.bf16.bf16.f32 "
        "{%0,%1,%2,%3}, {%4,%5,%6,%7}, {%8,%9}, {%0,%1,%2,%3};\n"
        : "+f"(c[0]), "+f"(c[1]), "+f"(c[2]), "+f"(c[3])
        : "r"(a0), "r"(a1), "r"(a2), "r"(a3), "r"(b0), "r"(b1));
}

template <bool SPLIT_OUT>
__global__ __launch_bounds__(128) void gemm_pipe(
    const __nv_bfloat16* __restrict__ Ah,  // [M][K]
    const __nv_bfloat16* __restrict__ Al,
    const __nv_bfloat16* __restrict__ Bh,  // [N][K]
    const __nv_bfloat16* __restrict__ Bl,
    const float* __restrict__ bias,
    float* __restrict__ Cf,                 // if !SPLIT_OUT
    uint32_t* __restrict__ Chh,             // if SPLIT_OUT
    uint32_t* __restrict__ Chl,
    int M, int N, int K)
{
    extern __shared__ char dyn[];
    const uint32_t sbase = (uint32_t)__cvta_generic_to_shared(dyn);

    const int tid  = threadIdx.x;
    const int lane = tid & 31;
    const int warp = tid >> 5;       // 0..3
    const int gid  = lane >> 2;      // 0..7
    const int tig  = lane & 3;       // 0..3
    const int warpM = (warp & 1) * 32;
    const int warpN = (warp >> 1) * 32;

    const int m0 = blockIdx.y * 64;
    const int n0 = blockIdx.x * 64;

    // cp.async chunk mapping: 256 chunks per 64x32 tile; 2 per thread.
    const int r0 = tid >> 2;          // row for l=0: 0..31
    const int q0 = tid & 3;           // 16B col group (k 8q..8q+7)

    float acc[2][4][4];
#pragma unroll
    for (int mt = 0; mt < 2; mt++)
#pragma unroll
        for (int nt = 0; nt < 4; nt++)
#pragma unroll
            for (int r = 0; r < 4; r++)
                acc[mt][nt][r] = 0.f;

#define ISSUE(k0v, st)                                                         \
    do {                                                                       \
        uint32_t sb = sbase + (st) * STAGE_B;                                  \
        _Pragma("unroll")                                                      \
        for (int l = 0; l < 2; l++) {                                          \
            int row = r0 + 32 * l;                                             \
            uint32_t d = sb + row * SROW + q0 * 16;                            \
            size_t ga = (size_t)(m0 + row) * K + (k0v) + q0 * 8;               \
            size_t gb = (size_t)(n0 + row) * K + (k0v) + q0 * 8;               \
            cp16(d + OFF_AH, Ah + ga);                                         \
            cp16(d + OFF_AL, Al + ga);                                         \
            cp16(d + OFF_BH, Bh + gb);                                         \
            cp16(d + OFF_BL, Bl + gb);                                         \
        }                                                                      \
        CP_COMMIT();                                                           \
    } while (0)

#define LD32(off) (*reinterpret_cast<const uint32_t*>(dyn + (off)))

    // Prologue: fill 3 stages
    ISSUE(0, 0);
    ISSUE(32, 1);
    ISSUE(64, 2);

    const int NIT = K / 32;   // 24
    for (int t = 0; t < NIT; t++) {
        CP_WAIT2();
        __syncthreads();

        const uint32_t sb = (uint32_t)((t % NSTAGES) * STAGE_B);
#pragma unroll
        for (int ks = 0; ks < 2; ks++) {
            const int kb = ks * 8;     // k-pair offset

            uint32_t ah[2][4], al[2][4];
#pragma unroll
            for (int mt = 0; mt < 2; mt++) {
                const int rm = warpM + mt * 16 + gid;
                uint32_t b0 = sb + rm * SROW + (kb + tig) * 4;
                uint32_t b8 = sb + (rm + 8) * SROW + (kb + tig) * 4;
                ah[mt][0] = LD32(b0 + OFF_AH);
                ah[mt][1] = LD32(b8 + OFF_AH);
                ah[mt][2] = LD32(b0 + OFF_AH + 16);
                ah[mt][3] = LD32(b8 + OFF_AH + 16);
                al[mt][0] = LD32(b0 + OFF_AL);
                al[mt][1] = LD32(b8 + OFF_AL);
                al[mt][2] = LD32(b0 + OFF_AL + 16);
                al[mt][3] = LD32(b8 + OFF_AL + 16);
            }
            uint32_t bh[4][2], bl[4][2];
#pragma unroll
            for (int nt = 0; nt < 4; nt++) {
                const int nn = warpN + nt * 8 + gid;
                uint32_t b0 = sb + nn * SROW + (kb + tig) * 4;
                bh[nt][0] = LD32(b0 + OFF_BH);
                bh[nt][1] = LD32(b0 + OFF_BH + 16);
                bl[nt][0] = LD32(b0 + OFF_BL);
                bl[nt][1] = LD32(b0 + OFF_BL + 16);
            }

#pragma unroll
            for (int mt = 0; mt < 2; mt++)
#pragma unroll
                for (int nt = 0; nt < 4; nt++) {
                    mma_bf16(acc[mt][nt], ah[mt][0], ah[mt][1], ah[mt][2], ah[mt][3],
                             bh[nt][0], bh[nt][1]);
                    mma_bf16(acc[mt][nt], ah[mt][0], ah[mt][1], ah[mt][2], ah[mt][3],
                             bl[nt][0], bl[nt][1]);
                    mma_bf16(acc[mt][nt], al[mt][0], al[mt][1], al[mt][2], al[mt][3],
                             bh[nt][0], bh[nt][1]);
                }
        }
        __syncthreads();

        if (t + NSTAGES < NIT) {
            ISSUE((t + NSTAGES) * 32, t % NSTAGES);
        } else {
            CP_COMMIT();   // keep group count uniform
        }
    }

    // Epilogue: bias + tanh
#pragma unroll
    for (int mt = 0; mt < 2; mt++) {
#pragma unroll
        for (int nt = 0; nt < 4; nt++) {
            const int row = m0 + warpM + mt * 16 + gid;
            const int col = n0 + warpN + nt * 8 + tig * 2;
            float2 bv = *reinterpret_cast<const float2*>(bias + col);
            float o0 = tanhf(acc[mt][nt][0] + bv.x);
            float o1 = tanhf(acc[mt][nt][1] + bv.y);
            float o2 = tanhf(acc[mt][nt][2] + bv.x);
            float o3 = tanhf(acc[mt][nt][3] + bv.y);
            if (SPLIT_OUT) {
                float h0, l0, h1, l1;
                split1(o0, h0, l0);
                split1(o1, h1, l1);
                size_t idx = ((size_t)row * N + col) >> 1;
                Chh[idx] = pack_bf2(h0, h1);
                Chl[idx] = pack_bf2(l0, l1);
                split1(o2, h0, l0);
                split1(o3, h1, l1);
                size_t idx2 = ((size_t)(row + 8) * N + col) >> 1;
                Chh[idx2] = pack_bf2(h0, h1);
                Chl[idx2] = pack_bf2(l0, l1);
            } else {
                float2 w0; w0.x = o0; w0.y = o1;
                *reinterpret_cast<float2*>(Cf + (size_t)row * N + col) = w0;
                float2 w1; w1.x = o2; w1.y = o3;
                *reinterpret_cast<float2*>(Cf + (size_t)(row + 8) * N + col) = w1;
            }
        }
    }
#undef ISSUE
#undef LD32
}

// ---------------------------------------------------------------------------
// Launch
// ---------------------------------------------------------------------------
extern "C" void kernel_launch(void* const* d_in, const int* in_sizes, int n_in,
                              void* d_out, int out_size)
{
    const float* token_embeds = (const float*)d_in[0];
    const int*   attn_mask    = (const int*)  d_in[1];
    const float* W1           = (const float*)d_in[2];
    const float* b1           = (const float*)d_in[3];
    const float* W2           = (const float*)d_in[4];
    const float* b2           = (const float*)d_in[5];
    float*       out          = (float*)d_out;

    void *p_ph, *p_pl, *p_hh, *p_hl, *p_w1h, *p_w1l, *p_w2h, *p_w2l;
    cudaGetSymbolAddress(&p_ph,  g_pool_hi);
    cudaGetSymbolAddress(&p_pl,  g_pool_lo);
    cudaGetSymbolAddress(&p_hh,  g_hid_hi);
    cudaGetSymbolAddress(&p_hl,  g_hid_lo);
    cudaGetSymbolAddress(&p_w1h, g_w1t_hi);
    cudaGetSymbolAddress(&p_w1l, g_w1t_lo);
    cudaGetSymbolAddress(&p_w2h, g_w2t_hi);
    cudaGetSymbolAddress(&p_w2l, g_w2t_lo);

    cudaFuncSetAttribute(gemm_pipe<true>,
                         cudaFuncAttributeMaxDynamicSharedMemorySize, GEMM_SMEM);
    cudaFuncSetAttribute(gemm_pipe<false>,
                         cudaFuncAttributeMaxDynamicSharedMemorySize, GEMM_SMEM);

    // 1) masked sum pooling -> bf16 hi/lo
    pool_kernel<<<BATCH, 384>>>(token_embeds, attn_mask);

    // 1b) weight transpose + split (independent of pool; serial stream is fine)
    dim3 cgrid(DIM / 32, DIM / 32, 2);
    convert_w_kernel<<<cgrid, dim3(32, 8)>>>(W1, W2);

    // 2) hidden = tanh(pooled @ W1 + b1) -> bf16 hi/lo
    dim3 grid1(DIM / 64, BATCH / 64);   // (12, 16) = 192 blocks
    gemm_pipe<true><<<grid1, 128, GEMM_SMEM>>>(
        (const __nv_bfloat16*)p_ph, (const __nv_bfloat16*)p_pl,
        (const __nv_bfloat16*)p_w1h, (const __nv_bfloat16*)p_w1l,
        b1, nullptr, (uint32_t*)p_hh, (uint32_t*)p_hl, BATCH, DIM, DIM);

    // 3) out = tanh(hidden @ W2 + b2) -> fp32
    gemm_pipe<false><<<grid1, 128, GEMM_SMEM>>>(
        (const __nv_bfloat16*)p_hh, (const __nv_bfloat16*)p_hl,
        (const __nv_bfloat16*)p_w2h, (const __nv_bfloat16*)p_w2l,
        b2, out, nullptr, nullptr, BATCH, DIM, DIM);
}